// round 16
// baseline (speedup 1.0000x reference)
#include <cuda_runtime.h>

#define NLVL   16
#define LVLC   8               // levels per CTA (half)
#define WIDTH  1000
#define PADW   (WIDTH + 4)     // w in [-2, 1001]
#define PITCH  9               // float2 slots per w-row (72 B): scatters banks
#define TPB    640             // 20 warps; 2 CTAs/SM -> 40 warps, 51-reg cap

#define TAB_OFF (PADW * PITCH * 8)   // 72288 B: G/H table after tap array

typedef unsigned long long u64;
typedef unsigned int       u32;

// ---------------- packed f32x2 helpers ----------------
__device__ __forceinline__ u64 pk(float lo, float hi) {
    u64 r; asm("mov.b64 %0, {%1,%2};" : "=l"(r) : "f"(lo), "f"(hi)); return r;
}
__device__ __forceinline__ void upk(float& lo, float& hi, u64 v) {
    asm("mov.b64 {%0,%1}, %2;" : "=f"(lo), "=f"(hi) : "l"(v));
}
__device__ __forceinline__ u64 f2fma(u64 a, u64 b, u64 c) {
    u64 r; asm("fma.rn.f32x2 %0, %1, %2, %3;" : "=l"(r) : "l"(a), "l"(b), "l"(c)); return r;
}
__device__ __forceinline__ u64 f2add(u64 a, u64 b) {
    u64 r; asm("add.rn.f32x2 %0, %1, %2;" : "=l"(r) : "l"(a), "l"(b)); return r;
}
__device__ __forceinline__ u64 f2sub(u64 a, u64 b) {
    u64 r; asm("sub.rn.f32x2 %0, %1, %2;" : "=l"(r) : "l"(a), "l"(b)); return r;
}
__device__ __forceinline__ u64 f2mul(u64 a, u64 b) {
    u64 r; asm("mul.rn.f32x2 %0, %1, %2;" : "=l"(r) : "l"(a), "l"(b)); return r;
}

__device__ __forceinline__ float hwsin(float r) {   // r in [-pi, pi]
    float s; asm("sin.approx.f32 %0, %1;" : "=f"(s) : "f"(r)); return s;
}

__device__ __forceinline__ u64 lds64(u32 addr, int imm_off) {
    u64 v;
    asm("ld.shared.b64 %0, [%1];" : "=l"(v) : "r"(addr + (u32)imm_off));
    return v;
}
__device__ __forceinline__ void lds128(u32 addr, int imm_off, u64& a, u64& b) {
    asm("ld.shared.v2.u64 {%0,%1}, [%2];"
        : "=l"(a), "=l"(b) : "r"(addr + (u32)imm_off));
}

__global__ __launch_bounds__(TPB, 2)
void trig_hash_kernel(const float* __restrict__ x,
                      const float* __restrict__ grids,
                      const float* __restrict__ G,
                      const float* __restrict__ H,
                      float2* __restrict__ out,
                      int n_items)     // B*4 : (sample, duo-within-half)
{
    extern __shared__ float2 gsm[];    // taps [w'][PITCH] + G/H table at TAB_OFF

    const int h    = blockIdx.x & 1;            // level half: levels 8h..8h+7
    const int slot = blockIdx.x >> 1;
    const int tid  = threadIdx.x;

    // Stage this half's 8 levels: gsm[(w+2)*PITCH + n_loc], zeros outside [0,W)
    for (int j = tid; j < PADW * LVLC; j += TPB) {
        int n_loc = j & (LVLC - 1);
        int w = (j >> 3) - 2;
        int n = LVLC * h + n_loc;
        float c0 = 0.f, c1 = 0.f;
        if ((unsigned)w < (unsigned)WIDTH) {
            c0 = grids[(n * 2 + 0) * WIDTH + w];
            c1 = grids[(n * 2 + 1) * WIDTH + w];
        }
        gsm[(w + 2) * PITCH + n_loc] = make_float2(c0, c1);
    }

    // Build G/H table: 8 combos (mm 0..3, oo 0..1) x 12 u64 (TURNS-scaled, packed)
    {
        const float S = 0.15915494309189535f;
        u64* tab = (u64*)((char*)gsm + TAB_OFF);
        if (tid < 96) {
            int combo = tid / 12;
            int j     = tid - combo * 12;
            int mm    = combo >> 1;
            int oo    = combo & 1;
            int n0g   = LVLC * h + 2 * mm + oo;
            int n1g   = LVLC * h + 2 * mm + 1 - oo;
            float v0, v1;
            if (j < 9) { v0 = G[j * 16 + n0g]; v1 = G[j * 16 + n1g]; }
            else       { v0 = H[(j - 9) * 16 + n0g]; v1 = H[(j - 9) * 16 + n1g]; }
            tab[combo * 12 + j] = pk(v0 * S, v1 * S);
        }
    }
    __syncthreads();

    const int glt    = slot * TPB + tid;
    const int stride = (gridDim.x >> 1) * TPB;    // multiple of 4
    const int mm     = tid & 3;                   // duo within half: levels 2mm,2mm+1
    const int o      = (tid >> 3) & 1;            // octet swap (bank spread)
    const int n0l    = 2 * mm + o;                // item-A local level
    const int n1l    = 2 * mm + 1 - o;            // item-B local level

    const u64 MAGIC = pk(12582912.0f, 12582912.0f);      // 1.5 * 2^23
    const u64 TWOPI = pk(6.2831853071795865f, 6.2831853071795865f);
    const u64 ONEp  = pk(1.0f, 1.0f);
    const u64 C075p = pk(0.75f, 0.75f);
    const u64 C125p = pk(1.25f, 1.25f);
    const float MAG499 = 12583411.0f;                    // 12582912 + 499, exact

    u32 smbase;
    asm("{ .reg .u64 t; cvta.to.shared.u64 t, %1; cvt.u32.u64 %0, t; }"
        : "=r"(smbase) : "l"(gsm));
    // tap0 byte addr = bits(bb)*72 + addrc   (72*0x4B400000 folds mod 2^32)
    const u32 addrc0 = smbase + 72u + (u32)(8 * n0l) - 1262485504u * 72u;
    const u32 addrc1 = smbase + 72u + (u32)(8 * n1l) - 1262485504u * 72u;
    const u32 tabad  = smbase + (u32)TAB_OFF + (u32)((2 * mm + o) * 96);

    // ---- preload x for the first iteration ----
    float q0, q1, q2;
    {
        const float* xp = x + 3 * (((glt < n_items) ? glt : 0) >> 2);
        q0 = xp[0]; q1 = xp[1]; q2 = xp[2];
    }

    for (int p = glt; p < n_items; p += stride) {
        // ---- prefetch next iteration's x ----
        int pn = p + stride;
        const float* xn = x + 3 * ((((pn < n_items) ? pn : p)) >> 2);
        float f0 = xn[0], f1 = xn[1], f2v = xn[2];

        // ---- reload G/H packed constants (broadcast LDS.128; frees regs) ----
        u64 G00, G01, G02, G10, G11, G12, G20, G21, G22, Hh0, Hh1, Hh2;
        lds128(tabad,  0, G00, G01);
        lds128(tabad, 16, G02, G10);
        lds128(tabad, 32, G11, G12);
        lds128(tabad, 48, G20, G21);
        lds128(tabad, 64, G22, Hh0);
        lds128(tabad, 80, Hh1, Hh2);

        // ---- broadcast-sample packed a-chain (turns) : lo=n0, hi=n1 ----
        u64 X0 = pk(q0, q0);
        u64 X1 = pk(q1, q1);
        u64 X2 = pk(q2, q2);
        u64 a0 = f2fma(X0, G00, f2fma(X1, G10, f2fma(X2, G20, Hh0)));
        u64 a1 = f2fma(X0, G01, f2fma(X1, G11, f2fma(X2, G21, Hh1)));
        u64 a2 = f2fma(X0, G02, f2fma(X1, G12, f2fma(X2, G22, Hh2)));

        // turns reduction: rt = a - rint(a) (exact), then *2pi
        u64 kb0 = f2add(a0, MAGIC), kb1 = f2add(a1, MAGIC), kb2 = f2add(a2, MAGIC);
        u64 rr0 = f2mul(f2sub(a0, f2sub(kb0, MAGIC)), TWOPI);
        u64 rr1 = f2mul(f2sub(a1, f2sub(kb1, MAGIC)), TWOPI);
        u64 rr2 = f2mul(f2sub(a2, f2sub(kb2, MAGIC)), TWOPI);
        float r0A, r0B, r1A, r1B, r2A, r2B;
        upk(r0A, r0B, rr0); upk(r1A, r1B, rr1); upk(r2A, r2B, rr2);

        float gxA = hwsin(r0A) * hwsin(r1A) * hwsin(r2A);   // level n0
        float gxB = hwsin(r0B) * hwsin(r1B) * hwsin(r2B);   // level n1

        // fused ix chain: ix = 500*gx + 499.5
        float bbA = fmaf(gxA, 500.0f, MAG499);        // MAGIC + floor(ix)
        float bbB = fmaf(gxB, 500.0f, MAG499);
        float xfA = bbA - 12582912.0f;
        float xfB = bbB - 12582912.0f;
        float tA  = fmaf(gxA, 500.0f, 499.5f - xfA);  // t = ix - base
        float tB  = fmaf(gxB, 500.0f, 499.5f - xfB);

        // ---- 8 channel-packed tap loads (pitch 72 B) ----
        const u32 adA = __float_as_uint(bbA) * 72u + addrc0;
        const u32 adB = __float_as_uint(bbB) * 72u + addrc1;
        u64 vA0 = lds64(adA,  0), vA1 = lds64(adA,  72);
        u64 vA2 = lds64(adA, 144), vA3 = lds64(adA, 216);
        u64 vB0 = lds64(adB,  0), vB1 = lds64(adB,  72);
        u64 vB2 = lds64(adB, 144), vB3 = lds64(adB, 216);

        // ---- packed cubic weights (n0 in lo, n1 in hi), u = t^2 - t ----
        u64 tp  = pk(tA, tB);
        u64 tm1 = f2sub(tp, ONEp);
        u64 u   = f2mul(tp, tm1);
        u64 v   = f2mul(C075p, u);
        u64 W3  = f2mul(v, tp);
        u64 W0  = f2sub(v, W3);
        u64 omt = f2sub(ONEp, tp);
        u64 z   = f2mul(u, tp);
        u64 hh  = f2sub(omt, u);
        u64 W1  = f2fma(C125p, z, hh);
        u64 r_  = f2sub(ONEp, W0);
        r_      = f2sub(r_, W1);
        u64 W2  = f2sub(r_, W3);

        float w0A,w0B,w1A,w1B,w2A,w2B,w3A,w3B;
        upk(w0A, w0B, W0); upk(w1A, w1B, W1);
        upk(w2A, w2B, W2); upk(w3A, w3B, W3);

        // ---- channel-packed accumulation ----
        u64 accA = f2mul(vA3, pk(w3A, w3A));          // level n0
        accA = f2fma(vA2, pk(w2A, w2A), accA);
        accA = f2fma(vA1, pk(w1A, w1A), accA);
        accA = f2fma(vA0, pk(w0A, w0A), accA);
        u64 accB = f2mul(vB3, pk(w3B, w3B));          // level n1
        accB = f2fma(vB2, pk(w2B, w2B), accB);
        accB = f2fma(vB1, pk(w1B, w1B), accB);
        accB = f2fma(vB0, pk(w0B, w0B), accB);

        // ull2 out index = 8s + 4h + mm = 2p - mm + 4h ; (levels 2mm, 2mm+1)
        ulonglong2 ov;
        ov.x = o ? accB : accA;
        ov.y = o ? accA : accB;
        ((ulonglong2*)out)[2 * p - mm + 4 * h] = ov;

        // rotate x
        q0 = f0; q1 = f1; q2 = f2v;
    }
}

extern "C" void kernel_launch(void* const* d_in, const int* in_sizes, int n_in,
                              void* d_out, int out_size)
{
    const float* x     = (const float*)d_in[0];
    const float* grids = (const float*)d_in[1];
    const float* G     = (const float*)d_in[2];
    const float* H     = (const float*)d_in[3];
    (void)n_in; (void)out_size;

    const int B       = in_sizes[0] / 3;
    const int n_items = B * 4;           // (sample, duo) items per level-half

    const int smem_bytes = TAB_OFF + 8 * 96 + 64;   // taps + G/H table

    cudaFuncSetAttribute(trig_hash_kernel,
                         cudaFuncAttributeMaxDynamicSharedMemorySize, smem_bytes);

    int sm_count = 148;
    cudaDeviceGetAttribute(&sm_count, cudaDevAttrMultiProcessorCount, 0);

    trig_hash_kernel<<<2 * sm_count, TPB, smem_bytes>>>(
        x, grids, G, H, (float2*)d_out, n_items);
}